// round 13
// baseline (speedup 1.0000x reference)
#include <cuda_runtime.h>
#include <cuda_bf16.h>
#include <cuda_fp8.h>
#include <cstdint>

// ---------------------------------------------------------------------------
// SSA — B=32, C=512, N=1024. FP8 mma.sync (m16n8k32 QMMA) version.
//   qkv conv : e4m3 x e4m3 GEMM, M=1536 (W,x scaled x16; BN scale-invariant),
//              epilogue: bf16 store + per-channel stats atomics
//   BN/LIF; q -> e4m3 q^T, k/v -> bitpacked; kv^T via AND+POPC -> e5m2
//   attn^T   : e4m3(q) x e5m2(kv) GEMM, fused spike epilogue -> e4m3
//   proj     : e4m3 x e4m3 GEMM (W x16, bias x16 in fp32), stats epilogue
//   BN/LIF -> d_out
// ---------------------------------------------------------------------------

namespace {
constexpr int  BB  = 32;
constexpr int  CC  = 512;
constexpr int  NN  = 1024;
constexpr long BCN = (long)BB * CC * NN;
constexpr long SY  = (long)3 * CC * NN;
constexpr float TAUf = 1.1f;
constexpr float EPSf = 1e-5f;
}

// scratch (device globals)
__device__ __nv_bfloat16 g_y[BB * 3 * CC * NN];     // qkv conv out (bf16, x256 scaled)
__device__ uint8_t       g_xT8[BB * CC * NN];       // x^T e4m3 (x16) [b][n][c]
__device__ uint8_t       g_qT8[BB * CC * NN];       // q spikes^T e4m3 [b][n][c]
__device__ unsigned      g_kbits[BB * CC * NN / 32];
__device__ unsigned      g_vbits[BB * CC * NN / 32];
__device__ uint8_t       g_kvT8[BB * CC * CC];      // kv^T e5m2 [b][d][c]
__device__ uint8_t       g_attnT8[BB * CC * NN];    // attn spikes e4m3 [b][n][d]
__device__ float         g_proj[BB * CC * NN];      // proj out fp32 (x16 scaled)
__device__ uint8_t       g_wqkv8[3 * CC * CC];      // stacked qkv weights e4m3 (x16)
__device__ uint8_t       g_pw8[CC * CC];            // proj weight e4m3 (x16)
__device__ float         g_ssum[4 * CC];
__device__ float         g_ssum2[4 * CC];
__device__ float         g_mean[4 * CC];
__device__ float         g_inv[4 * CC];

// ---------------------------------------------------------------------------
__device__ __forceinline__ uint32_t smem_u32(const void* p) {
    return (uint32_t)__cvta_generic_to_shared(p);
}
__device__ __forceinline__ void cp_async16(uint32_t s, const void* g) {
    asm volatile("cp.async.cg.shared.global [%0], [%1], 16;" :: "r"(s), "l"(g));
}
__device__ __forceinline__ void ldm_x4(uint32_t& r0, uint32_t& r1,
                                       uint32_t& r2, uint32_t& r3, uint32_t a) {
    asm volatile("ldmatrix.sync.aligned.m8n8.x4.shared.b16 {%0,%1,%2,%3}, [%4];"
                 : "=r"(r0), "=r"(r1), "=r"(r2), "=r"(r3) : "r"(a));
}
// FT: 0 = e4m3 x e4m3, 1 = e4m3 x e5m2 (both f32 accum, m16n8k32)
template<int FT>
__device__ __forceinline__ void mma_fp8(float* c, const uint32_t* a, const uint32_t* b) {
    if constexpr (FT == 0) {
        asm volatile(
            "mma.sync.aligned.m16n8k32.row.col.f32.e4m3.e4m3.f32 "
            "{%0,%1,%2,%3},{%4,%5,%6,%7},{%8,%9},{%0,%1,%2,%3};"
            : "+f"(c[0]), "+f"(c[1]), "+f"(c[2]), "+f"(c[3])
            : "r"(a[0]), "r"(a[1]), "r"(a[2]), "r"(a[3]), "r"(b[0]), "r"(b[1]));
    } else {
        asm volatile(
            "mma.sync.aligned.m16n8k32.row.col.f32.e4m3.e5m2.f32 "
            "{%0,%1,%2,%3},{%4,%5,%6,%7},{%8,%9},{%0,%1,%2,%3};"
            : "+f"(c[0]), "+f"(c[1]), "+f"(c[2]), "+f"(c[3])
            : "r"(a[0]), "r"(a[1]), "r"(a[2]), "r"(a[3]), "r"(b[0]), "r"(b[1]));
    }
}
__device__ __forceinline__ uint8_t f2e4m3(float f) {
    return (uint8_t)__nv_cvt_float_to_fp8(f, __NV_SATFINITE, __NV_E4M3);
}
__device__ __forceinline__ uint8_t f2e5m2(float f) {
    return (uint8_t)__nv_cvt_float_to_fp8(f, __NV_SATFINITE, __NV_E5M2);
}

// ---------------------------------------------------------------------------
// FP8 GEMM: C[m,n] = sum_k A[m][k] * BT[n][k]   (fp8 data viewed as u16 pairs)
//   lda/ldb/K/k-offsets in u16 units (1 u16 = 2 fp8 k-elements).
//   FT: 0 e4m3xe4m3, 1 e4m3xe5m2
//   EPI: 0 = bf16 store + stats, 1 = f32 store + 16*bias + stats,
//        2 = e4m3 spike store
// CTA tile 128x128(out) x K64(fp8)/chunk, 8 warps (64x32), double-buffered.
// ---------------------------------------------------------------------------
template<int FT, int EPI>
__global__ void __launch_bounds__(256)
gemm_fp8(const uint16_t* __restrict__ A, int lda, long sA,
         const uint16_t* __restrict__ BT, int ldb, long sB,
         void* __restrict__ Cout, int ldc, long sC,
         int K, const float* __restrict__ bias,
         float* __restrict__ ssum, float* __restrict__ ssum2)
{
    constexpr int LDS = 40;
    __shared__ uint16_t As[2][128 * LDS];
    __shared__ uint16_t Bs[2][128 * LDS];

    const int bz = blockIdx.z;
    const uint16_t* Ab = A + (long)bz * sA;
    const uint16_t* Bb = BT + (long)bz * sB;
    const int m0 = blockIdx.y * 128, n0 = blockIdx.x * 128;
    const int tid = threadIdx.x;
    const int lane = tid & 31, warp = tid >> 5;
    const int wm = (warp & 1) * 64, wn = (warp >> 1) * 32;

    float acc[4][4][4];
#pragma unroll
    for (int i = 0; i < 4; i++)
#pragma unroll
        for (int j = 0; j < 4; j++)
#pragma unroll
            for (int r = 0; r < 4; r++) acc[i][j][r] = 0.f;

    auto issue = [&](int st, int k0) {       // k0 in u16 units, chunk = 32 u16
#pragma unroll
        for (int i = 0; i < 2; i++) {
            int c = tid + i * 256;           // 0..511
            int row = c >> 2, kc = (c & 3) << 3;
            cp_async16(smem_u32(&As[st][row * LDS + kc]),
                       Ab + (long)(m0 + row) * lda + k0 + kc);
            cp_async16(smem_u32(&Bs[st][row * LDS + kc]),
                       Bb + (long)(n0 + row) * ldb + k0 + kc);
        }
        asm volatile("cp.async.commit_group;");
    };

    const int KT = K / 32;                   // K in u16; 32 u16 = 64 fp8 per chunk
    issue(0, 0);
    for (int kt = 0; kt < KT; kt++) {
        if (kt + 1 < KT) {
            issue((kt + 1) & 1, (kt + 1) * 32);
            asm volatile("cp.async.wait_group 1;");
        } else {
            asm volatile("cp.async.wait_group 0;");
        }
        __syncthreads();
        const uint16_t* as = As[kt & 1];
        const uint16_t* bs = Bs[kt & 1];
#pragma unroll
        for (int kk = 0; kk < 2; kk++) {     // each kk = 16 u16 = 32 fp8 k
            uint32_t af[4][4], bf[4][2];
#pragma unroll
            for (int mt = 0; mt < 4; mt++) {
                int row = wm + mt * 16 + (lane & 15);
                int kcol = kk * 16 + (lane >> 4) * 8;
                ldm_x4(af[mt][0], af[mt][1], af[mt][2], af[mt][3],
                       smem_u32(&as[row * LDS + kcol]));
            }
#pragma unroll
            for (int p = 0; p < 2; p++) {
                int g = lane >> 3;
                int row = wn + p * 16 + (g >> 1) * 8 + (lane & 7);
                int kcol = kk * 16 + (g & 1) * 8;
                uint32_t r0, r1, r2, r3;
                ldm_x4(r0, r1, r2, r3, smem_u32(&bs[row * LDS + kcol]));
                bf[p * 2][0] = r0; bf[p * 2][1] = r1;
                bf[p * 2 + 1][0] = r2; bf[p * 2 + 1][1] = r3;
            }
#pragma unroll
            for (int mt = 0; mt < 4; mt++)
#pragma unroll
                for (int nt = 0; nt < 4; nt++)
                    mma_fp8<FT>(acc[mt][nt], af[mt], bf[nt]);
        }
        __syncthreads();
    }

    // epilogue
#pragma unroll
    for (int mt = 0; mt < 4; mt++) {
        int row = m0 + wm + mt * 16 + (lane >> 2);
        float b0 = 0.f, b8 = 0.f;
        if (EPI == 1) { b0 = 16.f * bias[row]; b8 = 16.f * bias[row + 8]; }
        float sl = 0.f, ql = 0.f, sh = 0.f, qh = 0.f;
#pragma unroll
        for (int nt = 0; nt < 4; nt++) {
            int col = n0 + wn + nt * 8 + (lane & 3) * 2;
            float* a4 = acc[mt][nt];
            if (EPI == 2) {
                uint8_t* Cb = (uint8_t*)Cout + (long)bz * sC;
                uint8_t s0 = ((a4[0] * 0.125f) / TAUf - 0.5f >= 0.f) ? 0x38 : 0x00;
                uint8_t s1 = ((a4[1] * 0.125f) / TAUf - 0.5f >= 0.f) ? 0x38 : 0x00;
                uint8_t s2 = ((a4[2] * 0.125f) / TAUf - 0.5f >= 0.f) ? 0x38 : 0x00;
                uint8_t s3 = ((a4[3] * 0.125f) / TAUf - 0.5f >= 0.f) ? 0x38 : 0x00;
                *(unsigned short*)&Cb[(long)row * ldc + col] =
                    (unsigned short)(s0 | (s1 << 8));
                *(unsigned short*)&Cb[(long)(row + 8) * ldc + col] =
                    (unsigned short)(s2 | (s3 << 8));
            } else if (EPI == 0) {
                __nv_bfloat16* Cb = (__nv_bfloat16*)Cout + (long)bz * sC;
                float v0 = a4[0], v1 = a4[1], v2 = a4[2], v3 = a4[3];
                *(__nv_bfloat162*)&Cb[(long)row * ldc + col] = __floats2bfloat162_rn(v0, v1);
                *(__nv_bfloat162*)&Cb[(long)(row + 8) * ldc + col] = __floats2bfloat162_rn(v2, v3);
                sl += v0 + v1; ql = fmaf(v0, v0, fmaf(v1, v1, ql));
                sh += v2 + v3; qh = fmaf(v2, v2, fmaf(v3, v3, qh));
            } else {
                float* Cb = (float*)Cout + (long)bz * sC;
                float v0 = a4[0] + b0, v1 = a4[1] + b0;
                float v2 = a4[2] + b8, v3 = a4[3] + b8;
                *(float2*)&Cb[(long)row * ldc + col] = make_float2(v0, v1);
                *(float2*)&Cb[(long)(row + 8) * ldc + col] = make_float2(v2, v3);
                sl += v0 + v1; ql = fmaf(v0, v0, fmaf(v1, v1, ql));
                sh += v2 + v3; qh = fmaf(v2, v2, fmaf(v3, v3, qh));
            }
        }
        if (EPI != 2) {
            sl += __shfl_xor_sync(0xffffffffu, sl, 1);
            sl += __shfl_xor_sync(0xffffffffu, sl, 2);
            ql += __shfl_xor_sync(0xffffffffu, ql, 1);
            ql += __shfl_xor_sync(0xffffffffu, ql, 2);
            sh += __shfl_xor_sync(0xffffffffu, sh, 1);
            sh += __shfl_xor_sync(0xffffffffu, sh, 2);
            qh += __shfl_xor_sync(0xffffffffu, qh, 1);
            qh += __shfl_xor_sync(0xffffffffu, qh, 2);
            if ((lane & 3) == 0) {
                atomicAdd(&ssum[row], sl);  atomicAdd(&ssum2[row], ql);
                atomicAdd(&ssum[row + 8], sh); atomicAdd(&ssum2[row + 8], qh);
            }
        }
    }
}

// ---------------------------------------------------------------------------
__global__ void __launch_bounds__(256)
zero_stats(float* __restrict__ a, float* __restrict__ b)
{
    int i = blockIdx.x * 256 + threadIdx.x;
    if (i < 4 * CC) { a[i] = 0.f; b[i] = 0.f; }
}

__global__ void __launch_bounds__(256)
finalize_stats(const float* __restrict__ ss, const float* __restrict__ ss2,
               float* __restrict__ mean, float* __restrict__ inv, int nch)
{
    int i = blockIdx.x * 256 + threadIdx.x;
    if (i < nch) {
        const float invn = 1.f / (float)(BB * NN);
        float m = ss[i] * invn;
        float var = ss2[i] * invn - m * m;
        mean[i] = m;
        inv[i] = rsqrtf(var + EPSf);
    }
}

// weights -> e4m3 scaled x16 (BN per-channel scale-invariance absorbs it)
__global__ void __launch_bounds__(256)
convert_weights(const float* __restrict__ qw, const float* __restrict__ kw,
                const float* __restrict__ vw, const float* __restrict__ pw,
                uint8_t* __restrict__ wqkv, uint8_t* __restrict__ pwo)
{
    int i = blockIdx.x * 256 + threadIdx.x;
    wqkv[i]               = f2e4m3(16.f * qw[i]);
    wqkv[i + CC * CC]     = f2e4m3(16.f * kw[i]);
    wqkv[i + 2 * CC * CC] = f2e4m3(16.f * vw[i]);
    pwo[i]                = f2e4m3(16.f * pw[i]);
}

// x [b][c][n] fp32 -> xT e4m3 (x16) [b][n][c]
__global__ void __launch_bounds__(256)
xT_kernel(const float* __restrict__ x, uint8_t* __restrict__ xT)
{
    __shared__ float t[32][33];
    int b = blockIdx.z, n0 = blockIdx.x * 32, c0 = blockIdx.y * 32;
    int tx = threadIdx.x, ty = threadIdx.y;
    const float* xb = x + (long)b * CC * NN;
    uint8_t* ob = xT + (long)b * NN * CC;
#pragma unroll
    for (int i = 0; i < 32; i += 8)
        t[ty + i][tx] = xb[(long)(c0 + ty + i) * NN + n0 + tx];
    __syncthreads();
#pragma unroll
    for (int i = 0; i < 32; i += 8)
        ob[(long)(n0 + ty + i) * CC + c0 + tx] = f2e4m3(16.f * t[tx][ty + i]);
}

// q: BN + threshold + transpose -> e4m3 qT [b][n][c]
__global__ void __launch_bounds__(256)
spike_qT_kernel(const __nv_bfloat16* __restrict__ y, long bstride,
                const float* __restrict__ mean, const float* __restrict__ inv,
                uint8_t* __restrict__ qT)
{
    __shared__ float t[32][33];
    int b = blockIdx.z, n0 = blockIdx.x * 32, c0 = blockIdx.y * 32;
    int tx = threadIdx.x, ty = threadIdx.y;
    const __nv_bfloat16* yb = y + (long)b * bstride;
#pragma unroll
    for (int i = 0; i < 32; i += 8) {
        int c = c0 + ty + i;
        float v = __bfloat162float(yb[(long)c * NN + n0 + tx]);
        float bn = inv[c] * (v - mean[c]);
        t[ty + i][tx] = (bn / TAUf - 1.0f >= 0.f) ? 1.f : 0.f;
    }
    __syncthreads();
    uint8_t* ob = qT + (long)b * NN * CC;
#pragma unroll
    for (int i = 0; i < 32; i += 8)
        ob[(long)(n0 + ty + i) * CC + c0 + tx] = (t[tx][ty + i] != 0.f) ? 0x38 : 0x00;
}

// k/v: BN + threshold -> bitpacked (permuted-but-consistent layout)
__global__ void __launch_bounds__(256)
spike_pack_kernel(const __nv_bfloat16* __restrict__ y, long bstride,
                  const float* __restrict__ mean, const float* __restrict__ inv,
                  unsigned* __restrict__ bits)
{
    long t = (long)blockIdx.x * 256 + threadIdx.x;
    long e = t * 4;
    int b = (int)(e / ((long)CC * NN));
    long r = e - (long)b * CC * NN;
    int c = (int)(r >> 10);
    const __nv_bfloat16* p = y + (long)b * bstride + r;
    uint2 raw = *(const uint2*)p;
    __nv_bfloat162 p01 = *(__nv_bfloat162*)&raw.x;
    __nv_bfloat162 p23 = *(__nv_bfloat162*)&raw.y;
    float g = inv[c], m = mean[c];
    float v0 = __low2float(p01), v1 = __high2float(p01);
    float v2 = __low2float(p23), v3 = __high2float(p23);
    unsigned m0 = __ballot_sync(0xffffffffu, (g * (v0 - m)) / TAUf - 1.f >= 0.f);
    unsigned m1 = __ballot_sync(0xffffffffu, (g * (v1 - m)) / TAUf - 1.f >= 0.f);
    unsigned m2 = __ballot_sync(0xffffffffu, (g * (v2 - m)) / TAUf - 1.f >= 0.f);
    unsigned m3 = __ballot_sync(0xffffffffu, (g * (v3 - m)) / TAUf - 1.f >= 0.f);
    int lane = threadIdx.x & 31;
    long e0 = e - (long)lane * 4;
    unsigned w = (lane == 0) ? m0 : (lane == 1) ? m1 : (lane == 2) ? m2 : m3;
    if (lane < 4) bits[(e0 >> 5) + lane] = w;
}

// kvT[b][d][c] = popc over N of k_bits[c] & v_bits[d] -> e5m2
__global__ void __launch_bounds__(256)
kv_popc_kernel(const unsigned* __restrict__ kb, const unsigned* __restrict__ vb,
               uint8_t* __restrict__ kvT)
{
    __shared__ unsigned ks[32][65];
    __shared__ unsigned vs[32][65];
    const int bz = blockIdx.z;
    const int c0 = blockIdx.y * 64;
    const int d0 = blockIdx.x * 64;
    const unsigned* kbb = kb + (long)bz * CC * (NN / 32);
    const unsigned* vbb = vb + (long)bz * CC * (NN / 32);
    const int tid = threadIdx.x;
#pragma unroll
    for (int it = 0; it < 8; it++) {
        int idx = tid + it * 256;
        int r = idx >> 5, w = idx & 31;
        ks[w][r] = kbb[(long)(c0 + r) * 32 + w];
        vs[w][r] = vbb[(long)(d0 + r) * 32 + w];
    }
    __syncthreads();
    const int tm = (tid >> 4) * 4;   // c
    const int tn = (tid & 15) * 4;   // d
    int cnt[4][4];
#pragma unroll
    for (int i = 0; i < 4; i++)
#pragma unroll
        for (int j = 0; j < 4; j++) cnt[i][j] = 0;
#pragma unroll
    for (int w = 0; w < 32; w++) {
        unsigned a[4], b[4];
#pragma unroll
        for (int i = 0; i < 4; i++) a[i] = ks[w][tm + i];
#pragma unroll
        for (int j = 0; j < 4; j++) b[j] = vs[w][tn + j];
#pragma unroll
        for (int i = 0; i < 4; i++)
#pragma unroll
            for (int j = 0; j < 4; j++)
                cnt[i][j] += __popc(a[i] & b[j]);
    }
    uint8_t* ob = kvT + (long)bz * CC * CC;
#pragma unroll
    for (int j = 0; j < 4; j++) {
        long base = (long)(d0 + tn + j) * CC + c0 + tm;   // tm % 4 == 0
        unsigned pk = (unsigned)f2e5m2((float)cnt[0][j])
                    | ((unsigned)f2e5m2((float)cnt[1][j]) << 8)
                    | ((unsigned)f2e5m2((float)cnt[2][j]) << 16)
                    | ((unsigned)f2e5m2((float)cnt[3][j]) << 24);
        *(unsigned*)&ob[base] = pk;
    }
}

// final BN + LIF -> d_out
__global__ void __launch_bounds__(256)
spike_final_kernel(const float* __restrict__ y,
                   const float* __restrict__ mean, const float* __restrict__ inv,
                   float* __restrict__ out)
{
    long t = (long)blockIdx.x * 256 + threadIdx.x;
    long e = t * 4;
    int c = (int)((e >> 10) & (CC - 1));
    float g = inv[c], m = mean[c];
    float4 v = *(const float4*)&y[e];
    float4 o;
    o.x = ((g * (v.x - m)) / TAUf - 1.f >= 0.f) ? 1.f : 0.f;
    o.y = ((g * (v.y - m)) / TAUf - 1.f >= 0.f) ? 1.f : 0.f;
    o.z = ((g * (v.z - m)) / TAUf - 1.f >= 0.f) ? 1.f : 0.f;
    o.w = ((g * (v.w - m)) / TAUf - 1.f >= 0.f) ? 1.f : 0.f;
    *(float4*)&out[e] = o;
}

__global__ void __launch_bounds__(256)
fold_affine(float* __restrict__ mean, float* __restrict__ inv,
            const float* __restrict__ gamma, const float* __restrict__ beta, int nch)
{
    int i = blockIdx.x * 256 + threadIdx.x;
    if (i < nch) {
        float g = gamma[i] * inv[i];
        float m = mean[i];
        mean[i] = m - beta[i] / g;
        inv[i] = g;
    }
}

// ---------------------------------------------------------------------------
extern "C" void kernel_launch(void* const* d_in, const int* in_sizes, int n_in,
                              void* d_out, int out_size)
{
    const float* x      = (const float*)d_in[0];
    const float* q_w    = (const float*)d_in[1];
    const float* q_g    = (const float*)d_in[2];
    const float* q_b    = (const float*)d_in[3];
    const float* k_w    = (const float*)d_in[4];
    const float* k_g    = (const float*)d_in[5];
    const float* k_b    = (const float*)d_in[6];
    const float* v_w    = (const float*)d_in[7];
    const float* v_g    = (const float*)d_in[8];
    const float* v_b    = (const float*)d_in[9];
    const float* p_w    = (const float*)d_in[10];
    const float* p_g    = (const float*)d_in[11];
    const float* p_beta = (const float*)d_in[12];
    const float* p_bias = (const float*)d_in[13];

    void* p;
    cudaGetSymbolAddress(&p, g_y);      __nv_bfloat16* gy     = (__nv_bfloat16*)p;
    cudaGetSymbolAddress(&p, g_xT8);    uint8_t*       gxT    = (uint8_t*)p;
    cudaGetSymbolAddress(&p, g_qT8);    uint8_t*       gqT    = (uint8_t*)p;
    cudaGetSymbolAddress(&p, g_kbits);  unsigned*      gkb    = (unsigned*)p;
    cudaGetSymbolAddress(&p, g_vbits);  unsigned*      gvb    = (unsigned*)p;
    cudaGetSymbolAddress(&p, g_kvT8);   uint8_t*       gkvT   = (uint8_t*)p;
    cudaGetSymbolAddress(&p, g_attnT8); uint8_t*       gattT  = (uint8_t*)p;
    cudaGetSymbolAddress(&p, g_proj);   float*         gpr    = (float*)p;
    cudaGetSymbolAddress(&p, g_wqkv8);  uint8_t*       gwqkv  = (uint8_t*)p;
    cudaGetSymbolAddress(&p, g_pw8);    uint8_t*       gpw    = (uint8_t*)p;
    cudaGetSymbolAddress(&p, g_ssum);   float*         gss    = (float*)p;
    cudaGetSymbolAddress(&p, g_ssum2);  float*         gss2   = (float*)p;
    cudaGetSymbolAddress(&p, g_mean);   float*         gmean  = (float*)p;
    cudaGetSymbolAddress(&p, g_inv);    float*         ginv   = (float*)p;

    // strides in u16 units for fp8 operands (2 fp8 per u16)
    const int  ldK   = CC / 2;                 // 256 u16 per 512-fp8 row
    const long sB_x  = (long)NN * CC / 2;      // xT / qT / attnT per-batch (u16)
    const long sB_kv = (long)CC * CC / 2;      // kvT per-batch (u16)
    const long sCN   = (long)CC * NN;
    const unsigned nblk4 = (unsigned)(BCN / 4 / 256);
    dim3 t32(32, 8);
    dim3 gT(NN / 32, CC / 32, BB);

    // 0) zero stats, weight conversion, x transpose
    zero_stats<<<8, 256>>>(gss, gss2);
    convert_weights<<<(CC * CC) / 256, 256>>>(q_w, k_w, v_w, p_w, gwqkv, gpw);
    xT_kernel<<<gT, t32>>>(x, gxT);

    // 1) fused qkv conv GEMM (e4m3 x e4m3): M=1536, N=1024, K=512 fp8 (256 u16)
    gemm_fp8<0, 0><<<dim3(NN / 128, 1536 / 128, BB), 256>>>(
        (const uint16_t*)gwqkv, ldK, 0,
        (const uint16_t*)gxT, ldK, sB_x,
        gy, NN, SY, CC / 2, nullptr, gss, gss2);

    // 2) finalize qkv stats + fold affine
    finalize_stats<<<6, 256>>>(gss, gss2, gmean, ginv, 3 * CC);
    fold_affine<<<2, 256>>>(gmean + 0 * CC, ginv + 0 * CC, q_g, q_b, CC);
    fold_affine<<<2, 256>>>(gmean + 1 * CC, ginv + 1 * CC, k_g, k_b, CC);
    fold_affine<<<2, 256>>>(gmean + 2 * CC, ginv + 2 * CC, v_g, v_b, CC);

    // 3) spikes: q -> e4m3 transposed, k/v -> bitpacked
    spike_qT_kernel<<<gT, t32>>>(gy, SY, gmean, ginv, gqT);
    spike_pack_kernel<<<nblk4, 256>>>(gy + 1 * sCN, SY, gmean + 1 * CC, ginv + 1 * CC, gkb);
    spike_pack_kernel<<<nblk4, 256>>>(gy + 2 * sCN, SY, gmean + 2 * CC, ginv + 2 * CC, gvb);

    // 4) kv^T via popcount -> e5m2
    kv_popc_kernel<<<dim3(CC / 64, CC / 64, BB), 256>>>(gkb, gvb, gkvT);

    // 5) attn^T GEMM (e4m3 q x e5m2 kv) + spike: M=1024, N=512, K=512 fp8
    gemm_fp8<1, 2><<<dim3(CC / 128, NN / 128, BB), 256>>>(
        (const uint16_t*)gqT, ldK, sB_x,
        (const uint16_t*)gkvT, ldK, sB_kv,
        gattT, CC, sCN, CC / 2, nullptr, nullptr, nullptr);

    // 6) proj GEMM (e4m3 x e4m3) + 16*bias + stats: M=512, N=1024, K=512 fp8
    gemm_fp8<0, 1><<<dim3(NN / 128, CC / 128, BB), 256>>>(
        (const uint16_t*)gpw, ldK, 0,
        (const uint16_t*)gattT, ldK, sB_x,
        gpr, NN, sCN, CC / 2, p_bias, gss + 3 * CC, gss2 + 3 * CC);

    // 7) finalize proj stats + final spike
    finalize_stats<<<2, 256>>>(gss + 3 * CC, gss2 + 3 * CC,
                               gmean + 3 * CC, ginv + 3 * CC, CC);
    fold_affine<<<2, 256>>>(gmean + 3 * CC, ginv + 3 * CC, p_g, p_beta, CC);
    spike_final_kernel<<<nblk4, 256>>>(gpr, gmean + 3 * CC, ginv + 3 * CC,
                                       (float*)d_out);
}